// round 15
// baseline (speedup 1.0000x reference)
#include <cuda_runtime.h>

#define BB 128
#define TT 1024
#define CC 128
#define LL 128
#define SS 257
#define EPSF 1e-7f
#define NEGF -1e30f
#define LN2F 0.69314718055994530942f
#define KSTEP 8           // frames per phase (proven R11 geometry)
#define STRIDE 112        // warp state stride; halo = 4 lanes
#define RINGN 32          // prob rows per ring (4 phases deep)
#define SPAN 352          // 2*STRIDE + 128
#define NTHR 96

__device__ __forceinline__ float ex2f(float x){ float y; asm("ex2.approx.ftz.f32 %0,%1;":"=f"(y):"f"(x)); return y; }
__device__ __forceinline__ float lg2f(float x){ float y; asm("lg2.approx.f32 %0,%1;":"=f"(y):"f"(x)); return y; }
__device__ __forceinline__ void cp16(void* s, const void* g){
    unsigned sa = (unsigned)__cvta_generic_to_shared(s);
    asm volatile("cp.async.cg.shared.global [%0],[%1],16;"::"r"(sa),"l"(g):"memory");
}
__device__ __forceinline__ void cpcommit(){ asm volatile("cp.async.commit_group;":::"memory"); }
template<int N> __device__ __forceinline__ void cpwait(){ asm volatile("cp.async.wait_group %0;"::"n"(N):"memory"); }

// exact 2^d for d in [-126, 0]; 0 for d <= -127 (branchless clamp)
__device__ __forceinline__ float sc2(int d){
    int t = 127 + d;
    t = (t > 0) ? t : 0;
    return __int_as_float(t << 23);
}

__device__ __forceinline__ void issue_group(int q, int Tin, const float* __restrict__ yp,
                                            float (*ring)[CC], int tid)
{
    for (int c = tid; c < KSTEP * 32; c += NTHR) {
        int r  = c >> 5, ch = c & 31;
        int rg = q * KSTEP + r;
        if (rg < Tin)
            cp16(&ring[rg & (RINGN - 1)][ch * 4], yp + (size_t)rg * CC + ch * 4);
    }
    cpcommit();
}

// One fused 2-frame DP step (R11 semantics, verbatim)
__device__ __forceinline__ void fused_iter(
    float& xE0, float& xO0, float& xE1, float& xO1, int& Ei, bool& alive,
    float& A, float& Bv, float& Cv, int& Ep,
    float pB0, float p00, float p10, float pM0,
    float pB1, float p01, float p11,
    float skip0, float skip1, float skipM, bool w0l0, bool doShfl)
{
    float q1  = xO0 + xE0;
    float q2  = xE1 + xO0;
    float q3  = xO1 + xE1;
    float t3o = fmaf(skip1, xO0, q3);
    float t1o = fmaf(skipM, A, Bv + Cv);
    int   En = alive ? ((Ei > Ep) ? Ei : Ep) : Ep;
    float ss = alive ? sc2(Ei - En) : 0.0f;
    float sp = w0l0 ? 0.0f : sc2(Ep - En);
    float Cs = Cv * sp;
    float t1 = t1o * sp;
    float X1 = pM0 * t1;
    float u1 = fmaf(xE0, ss, Cs);
    float Y1 = pB0 * u1;
    float t2 = fmaf(q1, ss, skip0 * Cs);
    float X2 = p00 * t2;
    float Y2 = pB0 * (q2 * ss);
    float X3 = p10 * (t3o * ss);
    xE0 = pB1 * (Y1 + X1);
    xO0 = p01 * fmaf(skip0, X1, X2 + Y1);
    xE1 = pB1 * (Y2 + X2);
    xO1 = p11 * fmaf(skip1, X2, X3 + Y2);
    Ei = En;
    if (doShfl) {
        A  = __shfl_up_sync(0xffffffffu, xO0, 1);
        Bv = __shfl_up_sync(0xffffffffu, xE1, 1);
        Cv = __shfl_up_sync(0xffffffffu, xO1, 1);
        Ep = __shfl_up_sync(0xffffffffu, Ei, 1);
    }
    int mb = __float_as_int(fmaxf(fmaxf(xE0, xO0), fmaxf(xE1, xO1)));
    alive = (mb > 0);
    if (alive) {
        int e = (mb >> 23) - 127;
        float sc = __int_as_float((127 - e) << 23);
        xE0 *= sc; xO0 *= sc; xE1 *= sc; xO1 *= sc;
        Ei += e;
    }
}

// One single-frame DP step (R11 tail semantics, verbatim)
__device__ __forceinline__ void single_step(
    float& xE0, float& xO0, float& xE1, float& xO1, int& Ei,
    float pBt, float p0t, float p1t,
    float skip0, float skip1, bool w0l0)
{
    float pm = __shfl_up_sync(0xffffffffu, xO1, 1);
    int   Ex = __shfl_up_sync(0xffffffffu, Ei, 1);
    if (w0l0) pm = 0.0f;
    float mx = fmaxf(fmaxf(xE0, xO0), fmaxf(xE1, xO1));
    bool al = (__float_as_int(mx) > 0);
    int  En = al ? ((Ei > Ex) ? Ei : Ex) : Ex;
    float ss = al ? sc2(Ei - En) : 0.0f;
    float sp = sc2(Ex - En);
    float pmS = pm * sp;
    float e0 = xE0 * ss, o0 = xO0 * ss, e1 = xE1 * ss, o1 = xO1 * ss;
    xE0 = pBt * (e0 + pmS);
    xO0 = p0t * fmaf(skip0, pmS, o0 + e0);
    xE1 = pBt * (e1 + o0);
    xO1 = p1t * fmaf(skip1, o0, o1 + e1);
    Ei = En;
    int mb = __float_as_int(fmaxf(fmaxf(xE0, xO0), fmaxf(xE1, xO1)));
    if (mb > 0) {
        int e = (mb >> 23) - 127;
        float sc = __int_as_float((127 - e) << 23);
        xE0 *= sc; xO0 *= sc; xE1 *= sc; xO1 *= sc;
        Ei += e;
    }
}

__global__ __launch_bounds__(NTHR, 1)
void ctc_loss_kernel(const int* __restrict__ y_true,
                     const float* __restrict__ y_pred,
                     const int* __restrict__ input_len,
                     const int* __restrict__ label_len,
                     float* __restrict__ out)
{
    __shared__ __align__(16) float ringA[RINGN][CC];
    __shared__ __align__(16) float ringB[RINGN][CC];
    __shared__ float sbufA[2][SPAN];
    __shared__ float sbufB[2][SPAN];
    __shared__ int   sbEA[2][88];
    __shared__ int   sbEB[2][88];

    const int b0   = 2 * blockIdx.x;
    const int b1   = b0 + 1;
    const int tid  = threadIdx.x;
    const int w    = tid >> 5;
    const int lane = tid & 31;

    int TinA = input_len[b0]; if (TinA > TT) TinA = TT; if (TinA < 0) TinA = 0;
    int TinB = input_len[b1]; if (TinB > TT) TinB = TT; if (TinB < 0) TinB = 0;

    const int base = w * STRIDE;
    const int s0   = base + 4 * lane;
    const int eidx = w * 28 + lane;            // R11's proven sbE slot
    const int li0  = (base >> 1) + 2 * lane;
    const int li1  = li0 + 1;
    const int liM  = li0 - 1;
    const int cl0  = (li0 < LL) ? li0 : (LL - 1);
    const int cl1  = (li1 < LL) ? li1 : (LL - 1);
    int clM = liM; if (clM < 0) clM = 0; if (clM > LL - 1) clM = LL - 1;
    const bool w0l0 = (tid == 0);

    const int* ytA = y_true + b0 * LL;
    const int* ytB = y_true + b1 * LL;
    const int ext0A = ytA[cl0], ext1A = ytA[cl1], extMA = ytA[clM];
    const int ext0B = ytB[cl0], ext1B = ytB[cl1], extMB = ytB[clM];
    float skip0A = 0.0f, skip1A = 0.0f, skipMA = 0.0f;
    if (li0 >= 1 && li0 < LL && ext0A != ytA[li0 - 1]) skip0A = 1.0f;
    if (li1 < LL && ext1A != ext0A)                    skip1A = 1.0f;
    if (liM >= 1 && liM < LL && extMA != ytA[liM - 1]) skipMA = 1.0f;
    float skip0B = 0.0f, skip1B = 0.0f, skipMB = 0.0f;
    if (li0 >= 1 && li0 < LL && ext0B != ytB[li0 - 1]) skip0B = 1.0f;
    if (li1 < LL && ext1B != ext0B)                    skip1B = 1.0f;
    if (liM >= 1 && liM < LL && extMB != ytB[liM - 1]) skipMB = 1.0f;

    const float* __restrict__ ypA = y_pred + (size_t)b0 * TT * CC;
    const float* __restrict__ ypB = y_pred + (size_t)b1 * TT * CC;

    // per-element state machines (alpha = x * 2^Ei)
    float xE0A = (s0 == 0) ? 1.0f : 0.0f, xO0A = 0.0f, xE1A = 0.0f, xO1A = 0.0f;
    float xE0B = (s0 == 0) ? 1.0f : 0.0f, xO0B = 0.0f, xE1B = 0.0f, xO1B = 0.0f;
    int  EiA = 0, EiB = 0;
    bool aliveA = (tid == 0), aliveB = (tid == 0);

    // Tin==0 fallback stash (epilogue reads sbuf[(nph-1)&1] = sbuf[1] when nph==0)
    #pragma unroll
    for (int j = 0; j < 4; j++) {
        int s = s0 + j;
        if (s < SS) {
            float v = (s == 0) ? 0.0f : NEGF;
            sbufA[1][s] = v;
            sbufB[1][s] = v;
        }
    }

    issue_group(0, TinA, ypA, ringA, tid);
    issue_group(0, TinB, ypB, ringB, tid);
    issue_group(1, TinA, ypA, ringA, tid);
    issue_group(1, TinB, ypB, ringB, tid);
    issue_group(2, TinA, ypA, ringA, tid);
    issue_group(2, TinB, ypB, ringB, tid);
    cpwait<4>();
    __syncthreads();

    const int nphA = (TinA + KSTEP - 1) / KSTEP;
    const int nphB = (TinB + KSTEP - 1) / KSTEP;
    const int nph  = (nphA > nphB) ? nphA : nphB;

    // boundary shfl (both elements)
    float AA = __shfl_up_sync(0xffffffffu, xO0A, 1);
    float BvA = __shfl_up_sync(0xffffffffu, xE1A, 1);
    float CvA = __shfl_up_sync(0xffffffffu, xO1A, 1);
    int   EpA = __shfl_up_sync(0xffffffffu, EiA, 1);
    float AB = __shfl_up_sync(0xffffffffu, xO0B, 1);
    float BvB = __shfl_up_sync(0xffffffffu, xE1B, 1);
    float CvB = __shfl_up_sync(0xffffffffu, xO1B, 1);
    int   EpB = __shfl_up_sync(0xffffffffu, EiB, 1);

    for (int ph = 0; ph < nph; ph++) {
        const int t0 = ph * KSTEP;
        int kA = TinA - t0; if (kA > KSTEP) kA = KSTEP;
        int kB = TinB - t0; if (kB > KSTEP) kB = KSTEP;
        const bool actA = (kA > 0), actB = (kB > 0);
        const bool fullA = (kA == KSTEP), fullB = (kB == KSTEP);
        const bool lastA = actA && (ph == nphA - 1);
        const bool lastB = actB && (ph == nphB - 1);
        const int par = ph & 1;

        if (fullA && fullB) {
            // dominant path: both elements full — interleave the two chains
            float pBA[8], p0A[8], p1A[8], pMA[4];
            float pBB[8], p0B[8], p1B[8], pMB[4];
            #pragma unroll
            for (int k = 0; k < 8; k++) {
                const float* ra = ringA[(t0 + k) & (RINGN - 1)];
                pBA[k] = ra[CC - 1] + EPSF; p0A[k] = ra[ext0A] + EPSF; p1A[k] = ra[ext1A] + EPSF;
                const float* rb = ringB[(t0 + k) & (RINGN - 1)];
                pBB[k] = rb[CC - 1] + EPSF; p0B[k] = rb[ext0B] + EPSF; p1B[k] = rb[ext1B] + EPSF;
            }
            #pragma unroll
            for (int j = 0; j < 4; j++) {
                pMA[j] = ringA[(t0 + 2 * j) & (RINGN - 1)][extMA] + EPSF;
                pMB[j] = ringB[(t0 + 2 * j) & (RINGN - 1)][extMB] + EPSF;
            }
            #pragma unroll
            for (int j = 0; j < 4; j++) {
                fused_iter(xE0A, xO0A, xE1A, xO1A, EiA, aliveA, AA, BvA, CvA, EpA,
                           pBA[2*j], p0A[2*j], p1A[2*j], pMA[j],
                           pBA[2*j+1], p0A[2*j+1], p1A[2*j+1],
                           skip0A, skip1A, skipMA, w0l0, j < 3);
                fused_iter(xE0B, xO0B, xE1B, xO1B, EiB, aliveB, AB, BvB, CvB, EpB,
                           pBB[2*j], p0B[2*j], p1B[2*j], pMB[j],
                           pBB[2*j+1], p0B[2*j+1], p1B[2*j+1],
                           skip0B, skip1B, skipMB, w0l0, j < 3);
            }
        } else {
            if (fullA) {
                #pragma unroll
                for (int j = 0; j < 4; j++) {
                    const float* r0 = ringA[(t0 + 2 * j) & (RINGN - 1)];
                    const float* r1 = ringA[(t0 + 2 * j + 1) & (RINGN - 1)];
                    fused_iter(xE0A, xO0A, xE1A, xO1A, EiA, aliveA, AA, BvA, CvA, EpA,
                               r0[CC-1]+EPSF, r0[ext0A]+EPSF, r0[ext1A]+EPSF, r0[extMA]+EPSF,
                               r1[CC-1]+EPSF, r1[ext0A]+EPSF, r1[ext1A]+EPSF,
                               skip0A, skip1A, skipMA, w0l0, j < 3);
                }
            } else if (actA) {
                for (int k = 0; k < kA; k++) {
                    const float* rp = ringA[(t0 + k) & (RINGN - 1)];
                    single_step(xE0A, xO0A, xE1A, xO1A, EiA,
                                rp[CC-1]+EPSF, rp[ext0A]+EPSF, rp[ext1A]+EPSF,
                                skip0A, skip1A, w0l0);
                }
            }
            if (fullB) {
                #pragma unroll
                for (int j = 0; j < 4; j++) {
                    const float* r0 = ringB[(t0 + 2 * j) & (RINGN - 1)];
                    const float* r1 = ringB[(t0 + 2 * j + 1) & (RINGN - 1)];
                    fused_iter(xE0B, xO0B, xE1B, xO1B, EiB, aliveB, AB, BvB, CvB, EpB,
                               r0[CC-1]+EPSF, r0[ext0B]+EPSF, r0[ext1B]+EPSF, r0[extMB]+EPSF,
                               r1[CC-1]+EPSF, r1[ext0B]+EPSF, r1[ext1B]+EPSF,
                               skip0B, skip1B, skipMB, w0l0, j < 3);
                }
            } else if (actB) {
                for (int k = 0; k < kB; k++) {
                    const float* rp = ringB[(t0 + k) & (RINGN - 1)];
                    single_step(xE0B, xO0B, xE1B, xO1B, EiB,
                                rp[CC-1]+EPSF, rp[ext0B]+EPSF, rp[ext1B]+EPSF,
                                skip0B, skip1B, w0l0);
                }
            }
        }

        // ---- phase-end exchange (R11 logic, per element) ----
        if (actA) {
            if (!lastA) {
                if (lane >= 28) {
                    sbufA[par][s0]     = xE0A;
                    sbufA[par][s0 + 1] = xO0A;
                    sbufA[par][s0 + 2] = xE1A;
                    sbufA[par][s0 + 3] = xO1A;
                    sbEA[par][eidx] = EiA;
                }
            } else {
                float fE = (float)EiA;
                float l0 = fmaxf(lg2f(xE0A) + fE, NEGF);
                float l1 = fmaxf(lg2f(xO0A) + fE, NEGF);
                float l2 = fmaxf(lg2f(xE1A) + fE, NEGF);
                float l3 = fmaxf(lg2f(xO1A) + fE, NEGF);
                const int vmin = base + 2 * kA;
                if (s0     < SS && (w == 0 || s0     >= vmin)) sbufA[par][s0]     = l0;
                if (s0 + 1 < SS && (w == 0 || s0 + 1 >= vmin)) sbufA[par][s0 + 1] = l1;
                if (s0 + 2 < SS && (w == 0 || s0 + 2 >= vmin)) sbufA[par][s0 + 2] = l2;
                if (s0 + 3 < SS && (w == 0 || s0 + 3 >= vmin)) sbufA[par][s0 + 3] = l3;
            }
        }
        if (actB) {
            if (!lastB) {
                if (lane >= 28) {
                    sbufB[par][s0]     = xE0B;
                    sbufB[par][s0 + 1] = xO0B;
                    sbufB[par][s0 + 2] = xE1B;
                    sbufB[par][s0 + 3] = xO1B;
                    sbEB[par][eidx] = EiB;
                }
            } else {
                float fE = (float)EiB;
                float l0 = fmaxf(lg2f(xE0B) + fE, NEGF);
                float l1 = fmaxf(lg2f(xO0B) + fE, NEGF);
                float l2 = fmaxf(lg2f(xE1B) + fE, NEGF);
                float l3 = fmaxf(lg2f(xO1B) + fE, NEGF);
                const int vmin = base + 2 * kB;
                if (s0     < SS && (w == 0 || s0     >= vmin)) sbufB[par][s0]     = l0;
                if (s0 + 1 < SS && (w == 0 || s0 + 1 >= vmin)) sbufB[par][s0 + 1] = l1;
                if (s0 + 2 < SS && (w == 0 || s0 + 2 >= vmin)) sbufB[par][s0 + 2] = l2;
                if (s0 + 3 < SS && (w == 0 || s0 + 3 >= vmin)) sbufB[par][s0 + 3] = l3;
            }
        }

        cpwait<2>();            // rows for phase ph+1 (both elements) landed
        __syncthreads();        // publish sbuf/sbE + ring rows
        issue_group(ph + 3, TinA, ypA, ringA, tid);
        issue_group(ph + 3, TinB, ypB, ringB, tid);

        if (actA && !lastA) {
            if (w > 0 && lane < 4) {
                xE0A = sbufA[par][s0];
                xO0A = sbufA[par][s0 + 1];
                xE1A = sbufA[par][s0 + 2];
                xO1A = sbufA[par][s0 + 3];
                EiA  = sbEA[par][eidx];
                float mr = fmaxf(fmaxf(xE0A, xO0A), fmaxf(xE1A, xO1A));
                aliveA = (__float_as_int(mr) > 0);
            }
            AA  = __shfl_up_sync(0xffffffffu, xO0A, 1);
            BvA = __shfl_up_sync(0xffffffffu, xE1A, 1);
            CvA = __shfl_up_sync(0xffffffffu, xO1A, 1);
            EpA = __shfl_up_sync(0xffffffffu, EiA, 1);
        }
        if (actB && !lastB) {
            if (w > 0 && lane < 4) {
                xE0B = sbufB[par][s0];
                xO0B = sbufB[par][s0 + 1];
                xE1B = sbufB[par][s0 + 2];
                xO1B = sbufB[par][s0 + 3];
                EiB  = sbEB[par][eidx];
                float mr = fmaxf(fmaxf(xE0B, xO0B), fmaxf(xE1B, xO1B));
                aliveB = (__float_as_int(mr) > 0);
            }
            AB  = __shfl_up_sync(0xffffffffu, xO0B, 1);
            BvB = __shfl_up_sync(0xffffffffu, xE1B, 1);
            CvB = __shfl_up_sync(0xffffffffu, xO1B, 1);
            EpB = __shfl_up_sync(0xffffffffu, EiB, 1);
        }
    }

    cpwait<0>();
    __syncthreads();

    if (tid == 0) {
        {
            int lab = label_len[b0];
            if (lab < 0)  lab = 0;
            if (lab > LL) lab = LL;
            const float* fin = sbufA[(nphA - 1) & 1];
            float aL = fin[2 * lab];
            int ip = 2 * lab - 1; if (ip < 0) ip = 0;
            float aP = fin[ip];
            float mm = fmaxf(aL, aP);
            out[b0] = -LN2F * (mm + lg2f(ex2f(aL - mm) + ex2f(aP - mm)));
        }
        {
            int lab = label_len[b1];
            if (lab < 0)  lab = 0;
            if (lab > LL) lab = LL;
            const float* fin = sbufB[(nphB - 1) & 1];
            float aL = fin[2 * lab];
            int ip = 2 * lab - 1; if (ip < 0) ip = 0;
            float aP = fin[ip];
            float mm = fmaxf(aL, aP);
            out[b1] = -LN2F * (mm + lg2f(ex2f(aL - mm) + ex2f(aP - mm)));
        }
    }
}

extern "C" void kernel_launch(void* const* d_in, const int* in_sizes, int n_in,
                              void* d_out, int out_size) {
    const int*   y_true    = nullptr;
    const float* y_pred    = nullptr;
    const int*   input_len = nullptr;
    const int*   label_len = nullptr;
    for (int i = 0; i < n_in; ++i) {
        if (in_sizes[i] == BB * TT * CC)      y_pred = (const float*)d_in[i];
        else if (in_sizes[i] == BB * LL)      y_true = (const int*)d_in[i];
        else if (in_sizes[i] == BB) {
            if (!input_len) input_len = (const int*)d_in[i];
            else            label_len = (const int*)d_in[i];
        }
    }
    ctc_loss_kernel<<<BB / 2, NTHR>>>(y_true, y_pred, input_len, label_len, (float*)d_out);
}

// round 16
// speedup vs baseline: 1.6083x; 1.6083x over previous
#include <cuda_runtime.h>

#define BB 128
#define TT 1024
#define CC 128
#define LL 128
#define SS 257
#define EPSF 1e-7f
#define NEGF -1e30f
#define LN2F 0.69314718055994530942f
#define KSTEP 8           // frames per phase (proven R11 geometry)
#define STRIDE 112        // warp state stride; halo = 4 lanes
#define RING 32           // prob rows in cp.async ring (4 phases)
#define SPAN 352          // 2*STRIDE + 128
#define NTHR 96
#define NW 3

__device__ __forceinline__ float ex2f(float x){ float y; asm("ex2.approx.ftz.f32 %0,%1;":"=f"(y):"f"(x)); return y; }
__device__ __forceinline__ float lg2f(float x){ float y; asm("lg2.approx.f32 %0,%1;":"=f"(y):"f"(x)); return y; }
__device__ __forceinline__ void cp16(void* s, const void* g){
    unsigned sa = (unsigned)__cvta_generic_to_shared(s);
    asm volatile("cp.async.cg.shared.global [%0],[%1],16;"::"r"(sa),"l"(g):"memory");
}
__device__ __forceinline__ void cpcommit(){ asm volatile("cp.async.commit_group;":::"memory"); }
template<int N> __device__ __forceinline__ void cpwait(){ asm volatile("cp.async.wait_group %0;"::"n"(N):"memory"); }

// exact 2^d for d in [-126, 0]; 0 for d <= -127 (branchless clamp)
__device__ __forceinline__ float sc2(int d){
    int t = 127 + d;
    t = (t > 0) ? t : 0;
    return __int_as_float(t << 23);
}

__device__ __forceinline__ void issue_group(int q, int Tin, const float* __restrict__ yp,
                                            float (*ring)[CC], int tid)
{
    for (int c = tid; c < KSTEP * 32; c += NTHR) {
        int r  = c >> 5, ch = c & 31;
        int rg = q * KSTEP + r;
        if (rg < Tin)
            cp16(&ring[rg & (RING - 1)][ch * 4], yp + (size_t)rg * CC + ch * 4);
    }
    cpcommit();
}

__global__ __launch_bounds__(NTHR, 1)
void ctc_loss_kernel(const int* __restrict__ y_true,
                     const float* __restrict__ y_pred,
                     const int* __restrict__ input_len,
                     const int* __restrict__ label_len,
                     float* __restrict__ out)
{
    __shared__ __align__(16) float ring[RING][CC];
    __shared__ float sbuf[2][SPAN];
    __shared__ int   sbE[2][88];

    const int b    = blockIdx.x;
    const int tid  = threadIdx.x;
    const int w    = tid >> 5;
    const int lane = tid & 31;

    int Tin = input_len[b];
    if (Tin > TT) Tin = TT;
    if (Tin < 0)  Tin = 0;

    const int base = w * STRIDE;
    const int s0   = base + 4 * lane;
    const int eidx = w * 28 + lane;            // R11's proven sbE slot
    const int li0  = (base >> 1) + 2 * lane;   // label idx of odd state s0+1
    const int li1  = li0 + 1;                  // label idx of odd state s0+3
    const int liM  = li0 - 1;                  // label idx of odd state s0-1
    const int* yt  = y_true + b * LL;
    const int cl0  = (li0 < LL) ? li0 : (LL - 1);
    const int cl1  = (li1 < LL) ? li1 : (LL - 1);
    int clM = liM; if (clM < 0) clM = 0; if (clM > LL - 1) clM = LL - 1;
    const int ext0 = yt[cl0];
    const int ext1 = yt[cl1];
    const int extM = yt[clM];
    float skip0 = 0.0f, skip1 = 0.0f, skipM = 0.0f;
    if (li0 >= 1 && li0 < LL && ext0 != yt[li0 - 1]) skip0 = 1.0f;
    if (li1 < LL && ext1 != ext0)                    skip1 = 1.0f;
    if (liM >= 1 && liM < LL && extM != yt[liM - 1]) skipM = 1.0f;
    const bool w0l0 = (tid == 0);

    const float* __restrict__ yp_b = y_pred + (size_t)b * TT * CC;

    // alpha = x * 2^Ei; states: D=xE0(s0) E=xO0(s0+1) F=xE1(s0+2) G=xO1(s0+3)
    float xE0 = (s0 == 0) ? 1.0f : 0.0f;
    float xO0 = 0.0f, xE1 = 0.0f, xO1 = 0.0f;
    int   Ei  = 0;
    bool  alive = (tid == 0);

    // Tin==0 fallback stash
    #pragma unroll
    for (int j = 0; j < 4; j++) {
        int s = s0 + j;
        if (s < SS) sbuf[1][s] = (s == 0) ? 0.0f : NEGF;
    }

    issue_group(0, Tin, yp_b, ring, tid);
    issue_group(1, Tin, yp_b, ring, tid);
    issue_group(2, Tin, yp_b, ring, tid);
    cpwait<2>();
    __syncthreads();

    const int nph = (Tin + KSTEP - 1) / KSTEP;

    // boundary shfl: A=left xO0 (s0-3), Bv=left xE1 (s0-2), Cv=left xO1 (s0-1)
    float A  = __shfl_up_sync(0xffffffffu, xO0, 1);
    float Bv = __shfl_up_sync(0xffffffffu, xE1, 1);
    float Cv = __shfl_up_sync(0xffffffffu, xO1, 1);
    int   Ep = __shfl_up_sync(0xffffffffu, Ei, 1);

    for (int ph = 0; ph < nph; ph++) {
        const int t0   = ph * KSTEP;
        const int kmax = (Tin - t0 < KSTEP) ? (Tin - t0) : KSTEP;
        const bool lastp = (ph == nph - 1);
        const int par  = ph & 1;

        if (kmax == KSTEP) {
            // preload this phase's emissions (off the dependent chain)
            float pB[KSTEP], p0[KSTEP], p1[KSTEP], pM[4];
            #pragma unroll
            for (int k = 0; k < KSTEP; k++) {
                const float* rp = ring[(t0 + k) & (RING - 1)];
                pB[k] = rp[CC - 1] + EPSF;
                p0[k] = rp[ext0]   + EPSF;
                p1[k] = rp[ext1]   + EPSF;
            }
            #pragma unroll
            for (int j = 0; j < 4; j++)
                pM[j] = ring[(t0 + 2 * j) & (RING - 1)][extM] + EPSF;

            // straight-line 4 fused iters = 8 frames
            #pragma unroll
            for (int j = 0; j < 4; j++) {
                const int k0 = 2 * j, k1 = 2 * j + 1;
                // off-chain emission products (scheduled into shfl-wait window)
                float pB0 = pB[k0], pB1v = pB[k1];
                float p00 = p0[k0], p01v = p0[k1];
                float p10 = p1[k0], p11v = p1[k1];
                float pM0 = pM[j];
                float c0 = pB1v * pB0;
                float c1 = pB1v * pM0;
                float c2 = p01v * p00;
                float c3 = p01v * pB0;
                float c4 = (p01v * pM0) * skip0;
                float c5 = pB1v * p00;
                float c6 = (p11v * p00) * skip1;
                float c7 = p11v * p10;
                float c8 = p11v * pB0;
                // own-frame sums (independent of incoming shfl)
                float q1  = xO0 + xE0;
                float q2  = xE1 + xO0;
                float q3  = xO1 + xE1;
                float t3o = fmaf(skip1, xO0, q3);
                float t1o = fmaf(skipM, A, Bv + Cv);
                // frame resolution (alive carried from prior renorm)
                int   En = alive ? ((Ei > Ep) ? Ei : Ep) : Ep;
                float ss = alive ? sc2(Ei - En) : 0.0f;
                float sp = w0l0 ? 0.0f : sc2(Ep - En);
                float Cs = Cv * sp;
                float t1 = t1o * sp;
                float u1 = fmaf(xE0, ss, Cs);
                float t2 = fmaf(q1, ss, skip0 * Cs);
                float v2 = q2 * ss;
                float v3 = t3o * ss;
                xE0 = fmaf(c0, u1, c1 * t1);
                xO0 = fmaf(c2, t2, fmaf(c3, u1, c4 * t1));
                xE1 = fmaf(c0, v2, c5 * t2);
                xO1 = fmaf(c6, t2, fmaf(c7, v3, c8 * v2));
                Ei = En;
                if (j < 3) {
                    // early shfl; latency overlaps the renorm below
                    A  = __shfl_up_sync(0xffffffffu, xO0, 1);
                    Bv = __shfl_up_sync(0xffffffffu, xE1, 1);
                    Cv = __shfl_up_sync(0xffffffffu, xO1, 1);
                    Ep = __shfl_up_sync(0xffffffffu, Ei, 1);
                }
                // per-lane pow2 renorm (once per 2 frames)
                int mb = __float_as_int(fmaxf(fmaxf(xE0, xO0), fmaxf(xE1, xO1)));
                alive = (mb > 0);
                if (alive) {
                    int e = (mb >> 23) - 127;
                    float sc = __int_as_float((127 - e) << 23);
                    xE0 *= sc; xO0 *= sc; xE1 *= sc; xO1 *= sc;
                    Ei += e;
                }
            }
        } else {
            // tail phase (at most once): proven single-step loop
            for (int k = 0; k < kmax; k++) {
                const float* rp = ring[(t0 + k) & (RING - 1)];
                float pBt = rp[CC - 1] + EPSF;
                float p0t = rp[ext0]   + EPSF;
                float p1t = rp[ext1]   + EPSF;
                float pm = __shfl_up_sync(0xffffffffu, xO1, 1);
                int   Ex = __shfl_up_sync(0xffffffffu, Ei, 1);
                if (w0l0) pm = 0.0f;
                float mx = fmaxf(fmaxf(xE0, xO0), fmaxf(xE1, xO1));
                bool al = (__float_as_int(mx) > 0);
                int  En = al ? ((Ei > Ex) ? Ei : Ex) : Ex;
                float ss = al ? sc2(Ei - En) : 0.0f;
                float sp = sc2(Ex - En);
                float pmS = pm * sp;
                float e0 = xE0 * ss, o0 = xO0 * ss, e1 = xE1 * ss, o1 = xO1 * ss;
                xE0 = pBt * (e0 + pmS);
                xO0 = p0t * fmaf(skip0, pmS, o0 + e0);
                xE1 = pBt * (e1 + o0);
                xO1 = p1t * fmaf(skip1, o0, o1 + e1);
                Ei = En;
                int mb = __float_as_int(fmaxf(fmaxf(xE0, xO0), fmaxf(xE1, xO1)));
                alive = (mb > 0);
                if (alive) {
                    int e = (mb >> 23) - 127;
                    float sc = __int_as_float((127 - e) << 23);
                    xE0 *= sc; xO0 *= sc; xE1 *= sc; xO1 *= sc;
                    Ei += e;
                }
            }
        }

        // ---- phase-end exchange ----
        if (!lastp) {
            if (lane >= 28) {                  // halo for next warp's lanes 0..3
                sbuf[par][s0]     = xE0;
                sbuf[par][s0 + 1] = xO0;
                sbuf[par][s0 + 2] = xE1;
                sbuf[par][s0 + 3] = xO1;
                sbE[par][eidx] = Ei;
            }
        } else {
            float fE = (float)Ei;
            float l0 = fmaxf(lg2f(xE0) + fE, NEGF);
            float l1 = fmaxf(lg2f(xO0) + fE, NEGF);
            float l2 = fmaxf(lg2f(xE1) + fE, NEGF);
            float l3 = fmaxf(lg2f(xO1) + fE, NEGF);
            const int vmin = base + 2 * kmax;          // proven validity bound
            if (s0     < SS && (w == 0 || s0     >= vmin)) sbuf[par][s0]     = l0;
            if (s0 + 1 < SS && (w == 0 || s0 + 1 >= vmin)) sbuf[par][s0 + 1] = l1;
            if (s0 + 2 < SS && (w == 0 || s0 + 2 >= vmin)) sbuf[par][s0 + 2] = l2;
            if (s0 + 3 < SS && (w == 0 || s0 + 3 >= vmin)) sbuf[par][s0 + 3] = l3;
        }

        cpwait<1>();            // rows for phase ph+1 have landed
        __syncthreads();        // publish sbuf/sbE + ring rows
        issue_group(ph + 3, Tin, yp_b, ring, tid);

        if (!lastp) {
            if (w > 0 && lane < 4) {           // refresh left halo
                xE0 = sbuf[par][s0];
                xO0 = sbuf[par][s0 + 1];
                xE1 = sbuf[par][s0 + 2];
                xO1 = sbuf[par][s0 + 3];
                Ei  = sbE[par][eidx];
                float mr = fmaxf(fmaxf(xE0, xO0), fmaxf(xE1, xO1));
                alive = (__float_as_int(mr) > 0);
            }
            // boundary shfl with refreshed values
            A  = __shfl_up_sync(0xffffffffu, xO0, 1);
            Bv = __shfl_up_sync(0xffffffffu, xE1, 1);
            Cv = __shfl_up_sync(0xffffffffu, xO1, 1);
            Ep = __shfl_up_sync(0xffffffffu, Ei, 1);
        }
    }

    cpwait<0>();
    __syncthreads();

    if (tid == 0) {
        int lab = label_len[b];
        if (lab < 0)  lab = 0;
        if (lab > LL) lab = LL;
        const float* fin = sbuf[(nph - 1) & 1];
        float aL = fin[2 * lab];
        int ip = 2 * lab - 1; if (ip < 0) ip = 0;
        float aP = fin[ip];
        float mm = fmaxf(aL, aP);
        out[b] = -LN2F * (mm + lg2f(ex2f(aL - mm) + ex2f(aP - mm)));
    }
}

extern "C" void kernel_launch(void* const* d_in, const int* in_sizes, int n_in,
                              void* d_out, int out_size) {
    const int*   y_true    = nullptr;
    const float* y_pred    = nullptr;
    const int*   input_len = nullptr;
    const int*   label_len = nullptr;
    for (int i = 0; i < n_in; ++i) {
        if (in_sizes[i] == BB * TT * CC)      y_pred = (const float*)d_in[i];
        else if (in_sizes[i] == BB * LL)      y_true = (const int*)d_in[i];
        else if (in_sizes[i] == BB) {
            if (!input_len) input_len = (const int*)d_in[i];
            else            label_len = (const int*)d_in[i];
        }
    }
    ctc_loss_kernel<<<BB, NTHR>>>(y_true, y_pred, input_len, label_len, (float*)d_out);
}

// round 17
// speedup vs baseline: 1.7782x; 1.1056x over previous
#include <cuda_runtime.h>

#define BB 128
#define TT 1024
#define CC 128
#define LL 128
#define SS 257
#define EPSF 1e-7f
#define NEGF -1e30f
#define LN2F 0.69314718055994530942f
#define KSTEP 8           // frames per phase (proven R11 geometry)
#define STRIDE 112        // warp state stride; halo = 4 lanes
#define RING 32           // prob rows in cp.async ring (4 phases)
#define SPAN 352          // 2*STRIDE + 128
#define NTHR 96
#define NW 3

__device__ __forceinline__ float ex2f(float x){ float y; asm("ex2.approx.ftz.f32 %0,%1;":"=f"(y):"f"(x)); return y; }
__device__ __forceinline__ float lg2f(float x){ float y; asm("lg2.approx.f32 %0,%1;":"=f"(y):"f"(x)); return y; }
__device__ __forceinline__ void cp16(void* s, const void* g){
    unsigned sa = (unsigned)__cvta_generic_to_shared(s);
    asm volatile("cp.async.cg.shared.global [%0],[%1],16;"::"r"(sa),"l"(g):"memory");
}
__device__ __forceinline__ void cpcommit(){ asm volatile("cp.async.commit_group;":::"memory"); }
template<int N> __device__ __forceinline__ void cpwait(){ asm volatile("cp.async.wait_group %0;"::"n"(N):"memory"); }

// exact 2^d for d in [-126, 0]; 0 for d <= -127 (branchless clamp)
__device__ __forceinline__ float sc2(int d){
    int t = 127 + d;
    t = (t > 0) ? t : 0;
    return __int_as_float(t << 23);
}

__device__ __forceinline__ void issue_group(int q, int Tin, const float* __restrict__ yp,
                                            float (*ring)[CC], int tid)
{
    for (int c = tid; c < KSTEP * 32; c += NTHR) {
        int r  = c >> 5, ch = c & 31;
        int rg = q * KSTEP + r;
        if (rg < Tin)
            cp16(&ring[rg & (RING - 1)][ch * 4], yp + (size_t)rg * CC + ch * 4);
    }
    cpcommit();
}

__global__ __launch_bounds__(NTHR, 1)
void ctc_loss_kernel(const int* __restrict__ y_true,
                     const float* __restrict__ y_pred,
                     const int* __restrict__ input_len,
                     const int* __restrict__ label_len,
                     float* __restrict__ out)
{
    __shared__ __align__(16) float ring[RING][CC];
    __shared__ float sbuf[2][SPAN];
    __shared__ int   sbE[2][88];

    const int b    = blockIdx.x;
    const int tid  = threadIdx.x;
    const int w    = tid >> 5;
    const int lane = tid & 31;

    int Tin = input_len[b];
    if (Tin > TT) Tin = TT;
    if (Tin < 0)  Tin = 0;

    const int base = w * STRIDE;
    const int s0   = base + 4 * lane;
    const int eidx = w * 28 + lane;            // R11's proven sbE slot
    const int li0  = (base >> 1) + 2 * lane;   // label idx of odd state s0+1
    const int li1  = li0 + 1;                  // label idx of odd state s0+3
    const int* yt  = y_true + b * LL;
    const int cl0  = (li0 < LL) ? li0 : (LL - 1);
    const int cl1  = (li1 < LL) ? li1 : (LL - 1);
    const int ext0 = yt[cl0];
    const int ext1 = yt[cl1];
    // extM/pM still needed for the incoming odd-state emission (state s0-1's label)
    const int liM  = li0 - 1;
    int clM = liM; if (clM < 0) clM = 0; if (clM > LL - 1) clM = LL - 1;
    const int extM = yt[clM];
    float skip0 = 0.0f, skip1 = 0.0f;
    if (li0 >= 1 && li0 < LL && ext0 != yt[li0 - 1]) skip0 = 1.0f;
    if (li1 < LL && ext1 != ext0)                    skip1 = 1.0f;
    const bool w0l0 = (tid == 0);

    const float* __restrict__ yp_b = y_pred + (size_t)b * TT * CC;

    // alpha = x * 2^Ei; states: D=xE0(s0) E=xO0(s0+1) F=xE1(s0+2) G=xO1(s0+3)
    float xE0 = (s0 == 0) ? 1.0f : 0.0f;
    float xO0 = 0.0f, xE1 = 0.0f, xO1 = 0.0f;
    int   Ei  = 0;
    bool  alive = (tid == 0);

    // Tin==0 fallback stash
    #pragma unroll
    for (int j = 0; j < 4; j++) {
        int s = s0 + j;
        if (s < SS) sbuf[1][s] = (s == 0) ? 0.0f : NEGF;
    }

    issue_group(0, Tin, yp_b, ring, tid);
    issue_group(1, Tin, yp_b, ring, tid);
    issue_group(2, Tin, yp_b, ring, tid);
    cpwait<2>();
    __syncthreads();

    const int nph = (Tin + KSTEP - 1) / KSTEP;

    // boundary shfl: t3sh = left lane's t3o (== this lane's C+B+skipM*A),
    // Cv = left xO1 (s0-1), Ep = left exponent
    float t3b  = fmaf(skip1, xO0, xO1 + xE1);
    float t3sh = __shfl_up_sync(0xffffffffu, t3b, 1);
    float Cv   = __shfl_up_sync(0xffffffffu, xO1, 1);
    int   Ep   = __shfl_up_sync(0xffffffffu, Ei, 1);

    for (int ph = 0; ph < nph; ph++) {
        const int t0   = ph * KSTEP;
        const int kmax = (Tin - t0 < KSTEP) ? (Tin - t0) : KSTEP;
        const bool lastp = (ph == nph - 1);
        const int par  = ph & 1;

        if (kmax == KSTEP) {
            // preload this phase's emissions (off the dependent chain)
            float pB[KSTEP], p0[KSTEP], p1[KSTEP], pM[4];
            #pragma unroll
            for (int k = 0; k < KSTEP; k++) {
                const float* rp = ring[(t0 + k) & (RING - 1)];
                pB[k] = rp[CC - 1] + EPSF;
                p0[k] = rp[ext0]   + EPSF;
                p1[k] = rp[ext1]   + EPSF;
            }
            #pragma unroll
            for (int j = 0; j < 4; j++)
                pM[j] = ring[(t0 + 2 * j) & (RING - 1)][extM] + EPSF;

            // straight-line 4 fused iters = 8 frames
            #pragma unroll
            for (int j = 0; j < 4; j++) {
                const int k0 = 2 * j, k1 = 2 * j + 1;
                // own-frame sums
                float q1  = xO0 + xE0;
                float q2  = xE1 + xO0;
                float t3o = fmaf(skip1, xO0, xO1 + xE1);
                // frame resolution (alive carried fresh from last iter)
                int   En = alive ? ((Ei > Ep) ? Ei : Ep) : Ep;
                float ss = alive ? sc2(Ei - En) : 0.0f;
                float sp = w0l0 ? 0.0f : sc2(Ep - En);
                float Cs = Cv * sp;
                float t1 = t3sh * sp;              // incoming C+B+skipM*A, aligned
                float X1 = pM[j] * t1;
                float u1 = fmaf(xE0, ss, Cs);
                float Y1 = pB[k0] * u1;
                float t2 = fmaf(q1, ss, skip0 * Cs);
                float X2 = p0[k0] * t2;
                float Y2 = pB[k0] * (q2 * ss);
                float X3 = p1[k0] * (t3o * ss);
                xE0 = pB[k1] * (Y1 + X1);
                xO0 = p0[k1] * fmaf(skip0, X1, X2 + Y1);
                xE1 = pB[k1] * (Y2 + X2);
                xO1 = p1[k1] * fmaf(skip1, X2, X3 + Y2);
                Ei = En;
                if (j < 3) {
                    // early shfl of (t3o, Cv, Ei) in the pre-renorm frame
                    float t3u = fmaf(skip1, xO0, xO1 + xE1);
                    t3sh = __shfl_up_sync(0xffffffffu, t3u, 1);
                    Cv   = __shfl_up_sync(0xffffffffu, xO1, 1);
                    Ep   = __shfl_up_sync(0xffffffffu, Ei, 1);
                }
                // alive refreshed EVERY iter (revival mechanism, R9 lesson)
                int mb = __float_as_int(fmaxf(fmaxf(xE0, xO0), fmaxf(xE1, xO1)));
                alive = (mb > 0);
                // rescale every 2nd fused iter (4-frame cadence, proven by R7)
                if (j & 1) {
                    if (alive) {
                        int e = (mb >> 23) - 127;
                        float sc = __int_as_float((127 - e) << 23);
                        xE0 *= sc; xO0 *= sc; xE1 *= sc; xO1 *= sc;
                        Ei += e;
                    }
                }
            }
        } else {
            // tail phase (at most once): proven single-step loop
            for (int k = 0; k < kmax; k++) {
                const float* rp = ring[(t0 + k) & (RING - 1)];
                float pBt = rp[CC - 1] + EPSF;
                float p0t = rp[ext0]   + EPSF;
                float p1t = rp[ext1]   + EPSF;
                float pm = __shfl_up_sync(0xffffffffu, xO1, 1);
                int   Ex = __shfl_up_sync(0xffffffffu, Ei, 1);
                if (w0l0) pm = 0.0f;
                float mx = fmaxf(fmaxf(xE0, xO0), fmaxf(xE1, xO1));
                bool al = (__float_as_int(mx) > 0);
                int  En = al ? ((Ei > Ex) ? Ei : Ex) : Ex;
                float ss = al ? sc2(Ei - En) : 0.0f;
                float sp = sc2(Ex - En);
                float pmS = pm * sp;
                float e0 = xE0 * ss, o0 = xO0 * ss, e1 = xE1 * ss, o1 = xO1 * ss;
                xE0 = pBt * (e0 + pmS);
                xO0 = p0t * fmaf(skip0, pmS, o0 + e0);
                xE1 = pBt * (e1 + o0);
                xO1 = p1t * fmaf(skip1, o0, o1 + e1);
                Ei = En;
                int mb = __float_as_int(fmaxf(fmaxf(xE0, xO0), fmaxf(xE1, xO1)));
                alive = (mb > 0);
                if (alive) {
                    int e = (mb >> 23) - 127;
                    float sc = __int_as_float((127 - e) << 23);
                    xE0 *= sc; xO0 *= sc; xE1 *= sc; xO1 *= sc;
                    Ei += e;
                }
            }
        }

        // ---- phase-end exchange ----
        if (!lastp) {
            if (lane >= 28) {                  // halo for next warp's lanes 0..3
                sbuf[par][s0]     = xE0;
                sbuf[par][s0 + 1] = xO0;
                sbuf[par][s0 + 2] = xE1;
                sbuf[par][s0 + 3] = xO1;
                sbE[par][eidx] = Ei;
            }
        } else {
            float fE = (float)Ei;
            float l0 = fmaxf(lg2f(xE0) + fE, NEGF);
            float l1 = fmaxf(lg2f(xO0) + fE, NEGF);
            float l2 = fmaxf(lg2f(xE1) + fE, NEGF);
            float l3 = fmaxf(lg2f(xO1) + fE, NEGF);
            const int vmin = base + 2 * kmax;          // proven validity bound
            if (s0     < SS && (w == 0 || s0     >= vmin)) sbuf[par][s0]     = l0;
            if (s0 + 1 < SS && (w == 0 || s0 + 1 >= vmin)) sbuf[par][s0 + 1] = l1;
            if (s0 + 2 < SS && (w == 0 || s0 + 2 >= vmin)) sbuf[par][s0 + 2] = l2;
            if (s0 + 3 < SS && (w == 0 || s0 + 3 >= vmin)) sbuf[par][s0 + 3] = l3;
        }

        cpwait<1>();            // rows for phase ph+1 have landed
        __syncthreads();        // publish sbuf/sbE + ring rows
        issue_group(ph + 3, Tin, yp_b, ring, tid);

        if (!lastp) {
            if (w > 0 && lane < 4) {           // refresh left halo
                xE0 = sbuf[par][s0];
                xO0 = sbuf[par][s0 + 1];
                xE1 = sbuf[par][s0 + 2];
                xO1 = sbuf[par][s0 + 3];
                Ei  = sbE[par][eidx];
                float mr = fmaxf(fmaxf(xE0, xO0), fmaxf(xE1, xO1));
                alive = (__float_as_int(mr) > 0);
            }
            // boundary shfl with refreshed values
            float t3n = fmaf(skip1, xO0, xO1 + xE1);
            t3sh = __shfl_up_sync(0xffffffffu, t3n, 1);
            Cv   = __shfl_up_sync(0xffffffffu, xO1, 1);
            Ep   = __shfl_up_sync(0xffffffffu, Ei, 1);
        }
    }

    cpwait<0>();
    __syncthreads();

    if (tid == 0) {
        int lab = label_len[b];
        if (lab < 0)  lab = 0;
        if (lab > LL) lab = LL;
        const float* fin = sbuf[(nph - 1) & 1];
        float aL = fin[2 * lab];
        int ip = 2 * lab - 1; if (ip < 0) ip = 0;
        float aP = fin[ip];
        float mm = fmaxf(aL, aP);
        out[b] = -LN2F * (mm + lg2f(ex2f(aL - mm) + ex2f(aP - mm)));
    }
}

extern "C" void kernel_launch(void* const* d_in, const int* in_sizes, int n_in,
                              void* d_out, int out_size) {
    const int*   y_true    = nullptr;
    const float* y_pred    = nullptr;
    const int*   input_len = nullptr;
    const int*   label_len = nullptr;
    for (int i = 0; i < n_in; ++i) {
        if (in_sizes[i] == BB * TT * CC)      y_pred = (const float*)d_in[i];
        else if (in_sizes[i] == BB * LL)      y_true = (const int*)d_in[i];
        else if (in_sizes[i] == BB) {
            if (!input_len) input_len = (const int*)d_in[i];
            else            label_len = (const int*)d_in[i];
        }
    }
    ctc_loss_kernel<<<BB, NTHR>>>(y_true, y_pred, input_len, label_len, (float*)d_out);
}